// round 1
// baseline (speedup 1.0000x reference)
#include <cuda_runtime.h>
#include <math.h>

// ---------------- problem constants ----------------
#define NEMBD   2048
#define NH      16
#define DH      128
#define BATCH   2
#define SEQ     2048
#define MROWS   (BATCH*SEQ)     // 4096
#define QKV_N   (3*NEMBD)       // 6144

// ---------------- scratch (device globals, no runtime allocs) ----------------
__device__ float g_qkv[(size_t)MROWS * QKV_N];          // ~100 MB
__device__ float g_q[(size_t)BATCH*NH*SEQ*DH];          // 33.5 MB
__device__ float g_k[(size_t)BATCH*NH*SEQ*DH];
__device__ float g_v[(size_t)BATCH*NH*SEQ*DH];
__device__ float g_y[(size_t)MROWS * NEMBD];            // 33.5 MB
__device__ float g_cos[SEQ*64];
__device__ float g_sin[SEQ*64];

// ---------------- RoPE tables (fp64 angles: t up to 2047 amplifies ulp) -------
__global__ void rope_table_kernel(float* gcos, float* gsin) {
    int idx = blockIdx.x * blockDim.x + threadIdx.x;
    if (idx >= SEQ * 64) return;
    int t = idx >> 6;
    int i = idx & 63;
    double freq = exp(-((double)(2 * i) / 128.0) * log(10000.0));
    double ang = (double)t * freq;
    gcos[idx] = (float)cos(ang);
    gsin[idx] = (float)sin(ang);
}

// ---------------- SGEMM: C[M,N] = A[M,K] * W[N,K]^T  (both K-contiguous) -----
#define GBM 128
#define GBN 128
#define GBK 8

__global__ __launch_bounds__(256)
void sgemm_nt_kernel(const float* __restrict__ A, const float* __restrict__ W,
                     float* __restrict__ C, int M, int N, int K) {
    __shared__ float As[GBK][GBM];
    __shared__ float Ws[GBK][GBN];

    int tid = threadIdx.x;
    int tx = tid & 15;          // 0..15  -> N micro
    int ty = tid >> 4;          // 0..15  -> M micro
    int m0 = blockIdx.y * GBM;
    int n0 = blockIdx.x * GBN;

    int lrow = tid >> 1;        // 0..127
    int lk   = (tid & 1) * 4;   // 0 or 4

    const float* Aptr = A + (size_t)(m0 + lrow) * K + lk;
    const float* Wptr = W + (size_t)(n0 + lrow) * K + lk;

    float acc[8][8];
#pragma unroll
    for (int i = 0; i < 8; i++)
#pragma unroll
        for (int j = 0; j < 8; j++) acc[i][j] = 0.0f;

    for (int kt = 0; kt < K; kt += GBK) {
        float4 av = *(const float4*)(Aptr + kt);
        float4 wv = *(const float4*)(Wptr + kt);
        __syncthreads();
        As[lk + 0][lrow] = av.x; As[lk + 1][lrow] = av.y;
        As[lk + 2][lrow] = av.z; As[lk + 3][lrow] = av.w;
        Ws[lk + 0][lrow] = wv.x; Ws[lk + 1][lrow] = wv.y;
        Ws[lk + 2][lrow] = wv.z; Ws[lk + 3][lrow] = wv.w;
        __syncthreads();
#pragma unroll
        for (int k = 0; k < GBK; k++) {
            float4 a0 = *(const float4*)&As[k][ty * 8];
            float4 a1 = *(const float4*)&As[k][ty * 8 + 4];
            float4 b0 = *(const float4*)&Ws[k][tx * 8];
            float4 b1 = *(const float4*)&Ws[k][tx * 8 + 4];
            float a[8] = {a0.x, a0.y, a0.z, a0.w, a1.x, a1.y, a1.z, a1.w};
            float b[8] = {b0.x, b0.y, b0.z, b0.w, b1.x, b1.y, b1.z, b1.w};
#pragma unroll
            for (int i = 0; i < 8; i++)
#pragma unroll
                for (int j = 0; j < 8; j++)
                    acc[i][j] = fmaf(a[i], b[j], acc[i][j]);
        }
    }

#pragma unroll
    for (int i = 0; i < 8; i++) {
        float* Crow = C + (size_t)(m0 + ty * 8 + i) * N + n0 + tx * 8;
        *(float4*)Crow       = make_float4(acc[i][0], acc[i][1], acc[i][2], acc[i][3]);
        *(float4*)(Crow + 4) = make_float4(acc[i][4], acc[i][5], acc[i][6], acc[i][7]);
    }
}

// ---------------- RoPE apply + transpose to [B*H, T, D] ----------------------
__global__ void rope_apply_kernel(const float* __restrict__ qkv,
                                  const float* __restrict__ gcos,
                                  const float* __restrict__ gsin,
                                  float* __restrict__ q, float* __restrict__ k,
                                  float* __restrict__ v) {
    long long idx = (long long)blockIdx.x * blockDim.x + threadIdx.x;
    const long long total = (long long)BATCH * NH * SEQ * DH;
    if (idx >= total) return;
    int d  = (int)(idx & 127);
    int t  = (int)((idx >> 7) & (SEQ - 1));
    int bh = (int)(idx >> 18);            // 128*2048 = 2^18
    int b  = bh >> 4;
    int h  = bh & 15;

    size_t base = ((size_t)(b * SEQ + t)) * QKV_N + (size_t)h * DH;
    float qv = qkv[base + d];
    float kv = qkv[base + NEMBD + d];
    float vv = qkv[base + 2 * NEMBD + d];

    int ci = d & 63;
    float c = gcos[t * 64 + ci];
    float s = gsin[t * 64 + ci];
    float qr, kr;
    if (d < 64) {
        qr = -qkv[base + d + 64];
        kr = -qkv[base + NEMBD + d + 64];
    } else {
        qr = qkv[base + d - 64];
        kr = qkv[base + NEMBD + d - 64];
    }

    size_t o = ((size_t)bh * SEQ + t) * DH + d;
    q[o] = qv * c + qr * s;
    k[o] = kv * c + kr * s;
    v[o] = vv;
}

// ---------------- flash attention (fp32), BQ=128 BK=64 ----------------------
#define BQ 128
#define BKT 64
#define QTS_LD 132     // transposed Q rows (pad for banks, 16B-aligned)
#define KS_LD  129     // K rows padded (2-way max conflict on strided reads)
#define PS_LD  68      // P rows padded (16B-aligned)

#define FA_SMEM ((BQ*QTS_LD + BKT*KS_LD + BKT*DH + BQ*PS_LD) * 4)  // 168192 B

__global__ __launch_bounds__(256)
void flash_attn_kernel(const float* __restrict__ Qg, const float* __restrict__ Kg,
                       const float* __restrict__ Vg, float* __restrict__ Y) {
    extern __shared__ float sm[];
    float* Qts = sm;                         // [DH][QTS_LD]   (d-major, scaled)
    float* Ks  = Qts + BQ * QTS_LD;          // [BKT][KS_LD]
    float* Vs  = Ks + BKT * KS_LD;           // [BKT][DH]
    float* Ps  = Vs + BKT * DH;              // [BQ][PS_LD]

    int tid = threadIdx.x;
    int tc = tid & 15;        // S cols tc*4.., O/V cols tc*8..
    int tr = tid >> 4;        // rows tr*8..
    int qi = gridDim.x - 1 - blockIdx.x;     // big work units first
    int bh = blockIdx.y;
    int qbase = qi * BQ;

    const float* Qb = Qg + ((size_t)bh * SEQ + qbase) * DH;
    const float* Kb = Kg + (size_t)bh * SEQ * DH;
    const float* Vb = Vg + (size_t)bh * SEQ * DH;

    const float scale = 0.08838834764831845f;   // 1/sqrt(128), folded into Q

    // load + transpose Q (once per CTA)
    for (int idx = tid; idx < BQ * 32; idx += 256) {
        int row = idx >> 5, dq = idx & 31;
        float4 qv = *(const float4*)(Qb + (size_t)row * DH + dq * 4);
        Qts[(dq * 4 + 0) * QTS_LD + row] = qv.x * scale;
        Qts[(dq * 4 + 1) * QTS_LD + row] = qv.y * scale;
        Qts[(dq * 4 + 2) * QTS_LD + row] = qv.z * scale;
        Qts[(dq * 4 + 3) * QTS_LD + row] = qv.w * scale;
    }

    float m_i[8], l_i[8], o[8][8];
#pragma unroll
    for (int i = 0; i < 8; i++) {
        m_i[i] = -1e30f;
        l_i[i] = 0.0f;
#pragma unroll
        for (int j = 0; j < 8; j++) o[i][j] = 0.0f;
    }

    int nkt = 2 * qi + 2;
    for (int kt = 0; kt < nkt; kt++) {
        int kbase = kt * BKT;
        __syncthreads();   // prev PV done (and Q transpose on first iter)
        for (int idx = tid; idx < BKT * 32; idx += 256) {
            int row = idx >> 5, dq = idx & 31;
            float4 kv = *(const float4*)(Kb + (size_t)(kbase + row) * DH + dq * 4);
            Ks[row * KS_LD + dq * 4 + 0] = kv.x;
            Ks[row * KS_LD + dq * 4 + 1] = kv.y;
            Ks[row * KS_LD + dq * 4 + 2] = kv.z;
            Ks[row * KS_LD + dq * 4 + 3] = kv.w;
            float4 vv = *(const float4*)(Vb + (size_t)(kbase + row) * DH + dq * 4);
            *(float4*)&Vs[row * DH + dq * 4] = vv;
        }
        __syncthreads();

        // S = Q K^T  (8x4 per thread)
        float s[8][4];
#pragma unroll
        for (int i = 0; i < 8; i++)
#pragma unroll
            for (int j = 0; j < 4; j++) s[i][j] = 0.0f;

#pragma unroll 4
        for (int d = 0; d < DH; d++) {
            const float* qrow = &Qts[d * QTS_LD + tr * 8];
            float4 a0 = *(const float4*)qrow;
            float4 a1 = *(const float4*)(qrow + 4);
            float a[8] = {a0.x, a0.y, a0.z, a0.w, a1.x, a1.y, a1.z, a1.w};
            float b[4];
#pragma unroll
            for (int j = 0; j < 4; j++) b[j] = Ks[(tc * 4 + j) * KS_LD + d];
#pragma unroll
            for (int i = 0; i < 8; i++)
#pragma unroll
                for (int j = 0; j < 4; j++)
                    s[i][j] = fmaf(a[i], b[j], s[i][j]);
        }

        // causal mask (only the two diagonal-adjacent tiles need it)
        if (kbase + BKT - 1 > qbase) {
#pragma unroll
            for (int i = 0; i < 8; i++) {
                int qg = qbase + tr * 8 + i;
#pragma unroll
                for (int j = 0; j < 4; j++) {
                    int kg = kbase + tc * 4 + j;
                    if (kg > qg) s[i][j] = -1e30f;
                }
            }
        }

        // online softmax update (row groups = 16 consecutive lanes)
#pragma unroll
        for (int i = 0; i < 8; i++) {
            float mx = fmaxf(fmaxf(s[i][0], s[i][1]), fmaxf(s[i][2], s[i][3]));
            mx = fmaxf(mx, __shfl_xor_sync(0xffffffffu, mx, 8));
            mx = fmaxf(mx, __shfl_xor_sync(0xffffffffu, mx, 4));
            mx = fmaxf(mx, __shfl_xor_sync(0xffffffffu, mx, 2));
            mx = fmaxf(mx, __shfl_xor_sync(0xffffffffu, mx, 1));
            float mnew = fmaxf(m_i[i], mx);
            float alpha = __expf(m_i[i] - mnew);
            m_i[i] = mnew;
            float rs = 0.0f;
#pragma unroll
            for (int j = 0; j < 4; j++) {
                float p = __expf(s[i][j] - mnew);
                s[i][j] = p;
                rs += p;
            }
            rs += __shfl_xor_sync(0xffffffffu, rs, 8);
            rs += __shfl_xor_sync(0xffffffffu, rs, 4);
            rs += __shfl_xor_sync(0xffffffffu, rs, 2);
            rs += __shfl_xor_sync(0xffffffffu, rs, 1);
            l_i[i] = l_i[i] * alpha + rs;
#pragma unroll
            for (int j = 0; j < 8; j++) o[i][j] *= alpha;
        }

        // stage P
#pragma unroll
        for (int i = 0; i < 8; i++)
            *(float4*)&Ps[(tr * 8 + i) * PS_LD + tc * 4] =
                make_float4(s[i][0], s[i][1], s[i][2], s[i][3]);
        __syncthreads();

        // O += P V   (8x8 per thread)
#pragma unroll 2
        for (int k = 0; k < BKT; k++) {
            float4 v0 = *(const float4*)&Vs[k * DH + tc * 8];
            float4 v1 = *(const float4*)&Vs[k * DH + tc * 8 + 4];
            float vv[8] = {v0.x, v0.y, v0.z, v0.w, v1.x, v1.y, v1.z, v1.w};
#pragma unroll
            for (int i = 0; i < 8; i++) {
                float p = Ps[(tr * 8 + i) * PS_LD + k];
#pragma unroll
                for (int j = 0; j < 8; j++)
                    o[i][j] = fmaf(p, vv[j], o[i][j]);
            }
        }
    }

    // epilogue: O/l -> y[b, t, h*128 + c]
    int b = bh >> 4, h = bh & 15;
#pragma unroll
    for (int i = 0; i < 8; i++) {
        float inv = 1.0f / l_i[i];
        int tg = qbase + tr * 8 + i;
        float* yrow = Y + ((size_t)(b * SEQ + tg)) * NEMBD + h * DH + tc * 8;
        *(float4*)yrow       = make_float4(o[i][0] * inv, o[i][1] * inv,
                                           o[i][2] * inv, o[i][3] * inv);
        *(float4*)(yrow + 4) = make_float4(o[i][4] * inv, o[i][5] * inv,
                                           o[i][6] * inv, o[i][7] * inv);
    }
}

// ---------------- launch ------------------------------------------------------
extern "C" void kernel_launch(void* const* d_in, const int* in_sizes, int n_in,
                              void* d_out, int out_size) {
    const float* x      = (const float*)d_in[0];
    const float* w_qkv  = (const float*)d_in[1];
    const float* w_proj = (const float*)d_in[2];
    float* out = (float*)d_out;

    float *qkv, *q, *k, *v, *y, *gc, *gs;
    cudaGetSymbolAddress((void**)&qkv, g_qkv);
    cudaGetSymbolAddress((void**)&q, g_q);
    cudaGetSymbolAddress((void**)&k, g_k);
    cudaGetSymbolAddress((void**)&v, g_v);
    cudaGetSymbolAddress((void**)&y, g_y);
    cudaGetSymbolAddress((void**)&gc, g_cos);
    cudaGetSymbolAddress((void**)&gs, g_sin);

    // 1) RoPE tables
    rope_table_kernel<<<(SEQ * 64 + 255) / 256, 256>>>(gc, gs);

    // 2) QKV projection: [4096,2048] x [6144,2048]^T
    sgemm_nt_kernel<<<dim3(QKV_N / GBN, MROWS / GBM), 256>>>(
        x, w_qkv, qkv, MROWS, QKV_N, NEMBD);

    // 3) RoPE + transpose to [B*H, T, D]
    {
        long long total = (long long)BATCH * NH * SEQ * DH;
        rope_apply_kernel<<<(unsigned)((total + 255) / 256), 256>>>(qkv, gc, gs, q, k, v);
    }

    // 4) flash attention -> y [B,T,C]
    cudaFuncSetAttribute(flash_attn_kernel,
                         cudaFuncAttributeMaxDynamicSharedMemorySize, FA_SMEM);
    flash_attn_kernel<<<dim3(SEQ / BQ, BATCH * NH), 256, FA_SMEM>>>(q, k, v, y);

    // 5) output projection
    sgemm_nt_kernel<<<dim3(NEMBD / GBN, MROWS / GBM), 256>>>(
        y, w_proj, out, MROWS, NEMBD, NEMBD);
}

// round 3
// speedup vs baseline: 2.8300x; 2.8300x over previous
#include <cuda_runtime.h>
#include <cuda_bf16.h>
#include <math.h>
#include <stdint.h>

// ---------------- problem constants ----------------
#define NEMBD   2048
#define NH      16
#define DH      128
#define BATCH   2
#define SEQ     2048
#define MROWS   (BATCH*SEQ)     // 4096
#define QKV_N   (3*NEMBD)       // 6144

// ---------------- scratch (device globals, no runtime allocs) ----------------
__device__ float g_qkv[(size_t)MROWS * QKV_N];
__device__ float g_q[(size_t)BATCH*NH*SEQ*DH];
__device__ float g_k[(size_t)BATCH*NH*SEQ*DH];
__device__ float g_v[(size_t)BATCH*NH*SEQ*DH];
__device__ float g_y[(size_t)MROWS * NEMBD];
__device__ float g_cos[SEQ*64];
__device__ float g_sin[SEQ*64];

// ================= RoPE tables (fp64 angles) =================
__global__ void rope_table_kernel(float* gcos, float* gsin) {
    int idx = blockIdx.x * blockDim.x + threadIdx.x;
    if (idx >= SEQ * 64) return;
    int t = idx >> 6;
    int i = idx & 63;
    double freq = exp(-((double)(2 * i) / 128.0) * log(10000.0));
    double ang = (double)t * freq;
    gcos[idx] = (float)cos(ang);
    gsin[idx] = (float)sin(ang);
}

// ================= bf16-split HMMA GEMM ======================================
// C[M,N] = A[M,K] * W[N,K]^T, fp32 in/out.
// In-kernel split a = hi + lo (bf16 each); D += Ahi*Bhi + Ahi*Blo + Alo*Bhi.
// mma.sync.aligned.m16n8k16.row.col.f32.bf16.bf16.f32  (sm_80 ISA — compiles
// for plain sm_103; tcgen05 is rejected by this harness's PTX target).

#define MMA16816(d, a0, a1, a2, a3, b0, b1)                                \
    asm volatile(                                                          \
        "mma.sync.aligned.m16n8k16.row.col.f32.bf16.bf16.f32 "             \
        "{%0,%1,%2,%3}, {%4,%5,%6,%7}, {%8,%9}, {%0,%1,%2,%3};"            \
        : "+f"((d)[0]), "+f"((d)[1]), "+f"((d)[2]), "+f"((d)[3])           \
        : "r"(a0), "r"(a1), "r"(a2), "r"(a3), "r"(b0), "r"(b1))

__device__ __forceinline__ void bf16_split2(float x, float y,
                                            uint32_t& hi, uint32_t& lo) {
    __nv_bfloat162 h = __floats2bfloat162_rn(x, y);
    float rx = x - __bfloat162float(__low2bfloat16(h));
    float ry = y - __bfloat162float(__high2bfloat16(h));
    __nv_bfloat162 l = __floats2bfloat162_rn(rx, ry);
    hi = *(uint32_t*)&h;
    lo = *(uint32_t*)&l;
}

#define SLD 40   // smem row stride in bf16 elems (80 B): conflict-free frag reads

__global__ __launch_bounds__(256, 2)
void gemm_mma_kernel(const float* __restrict__ A, const float* __restrict__ W,
                     float* __restrict__ C, int M, int N, int K) {
    __shared__ __nv_bfloat16 AsH[128 * SLD];
    __shared__ __nv_bfloat16 AsL[128 * SLD];
    __shared__ __nv_bfloat16 BsH[128 * SLD];
    __shared__ __nv_bfloat16 BsL[128 * SLD];

    const int tid  = threadIdx.x;
    const int warp = tid >> 5, lane = tid & 31;
    const int g = lane >> 2, t = lane & 3;     // mma fragment coords
    const int wm = warp & 3, wn = warp >> 2;   // 4x2 warp grid; warp tile 32x64
    const int m0 = blockIdx.y * 128;
    const int n0 = blockIdx.x * 128;

    float acc[2][8][4];
#pragma unroll
    for (int mf = 0; mf < 2; mf++)
#pragma unroll
        for (int nf = 0; nf < 8; nf++)
#pragma unroll
            for (int r = 0; r < 4; r++) acc[mf][nf][r] = 0.0f;

    const int lrow = tid >> 1;          // 0..127
    const int lcg  = (tid & 1) * 16;    // col group 0 or 16
    const float* Ag = A + (size_t)(m0 + lrow) * K + lcg;
    const float* Wg = W + (size_t)(n0 + lrow) * K + lcg;

    for (int kt = 0; kt < K; kt += 32) {
        __syncthreads();   // previous mma phase done with smem
#pragma unroll
        for (int q = 0; q < 4; q++) {
            float4 av = *(const float4*)(Ag + kt + q * 4);
            uint32_t h01, l01, h23, l23;
            bf16_split2(av.x, av.y, h01, l01);
            bf16_split2(av.z, av.w, h23, l23);
            int idx = lrow * SLD + lcg + q * 4;
            *(uint2*)&AsH[idx] = make_uint2(h01, h23);
            *(uint2*)&AsL[idx] = make_uint2(l01, l23);

            float4 wv = *(const float4*)(Wg + kt + q * 4);
            bf16_split2(wv.x, wv.y, h01, l01);
            bf16_split2(wv.z, wv.w, h23, l23);
            *(uint2*)&BsH[idx] = make_uint2(h01, h23);
            *(uint2*)&BsL[idx] = make_uint2(l01, l23);
        }
        __syncthreads();

#pragma unroll
        for (int kk = 0; kk < 32; kk += 16) {
            uint32_t ah[2][4], al[2][4];
#pragma unroll
            for (int mf = 0; mf < 2; mf++) {
                int r = wm * 32 + mf * 16 + g;
                const __nv_bfloat16* ph = &AsH[r * SLD + kk + 2 * t];
                ah[mf][0] = *(const uint32_t*)ph;
                ah[mf][1] = *(const uint32_t*)(ph + 8 * SLD);
                ah[mf][2] = *(const uint32_t*)(ph + 8);
                ah[mf][3] = *(const uint32_t*)(ph + 8 * SLD + 8);
                const __nv_bfloat16* pl = &AsL[r * SLD + kk + 2 * t];
                al[mf][0] = *(const uint32_t*)pl;
                al[mf][1] = *(const uint32_t*)(pl + 8 * SLD);
                al[mf][2] = *(const uint32_t*)(pl + 8);
                al[mf][3] = *(const uint32_t*)(pl + 8 * SLD + 8);
            }
#pragma unroll
            for (int nf = 0; nf < 8; nf++) {
                int nr = wn * 64 + nf * 8 + g;
                const __nv_bfloat16* pbh = &BsH[nr * SLD + kk + 2 * t];
                uint32_t bh0 = *(const uint32_t*)pbh;
                uint32_t bh1 = *(const uint32_t*)(pbh + 8);
                const __nv_bfloat16* pbl = &BsL[nr * SLD + kk + 2 * t];
                uint32_t bl0 = *(const uint32_t*)pbl;
                uint32_t bl1 = *(const uint32_t*)(pbl + 8);
#pragma unroll
                for (int mf = 0; mf < 2; mf++) {
                    MMA16816(acc[mf][nf], ah[mf][0], ah[mf][1], ah[mf][2], ah[mf][3], bh0, bh1);
                    MMA16816(acc[mf][nf], ah[mf][0], ah[mf][1], ah[mf][2], ah[mf][3], bl0, bl1);
                    MMA16816(acc[mf][nf], al[mf][0], al[mf][1], al[mf][2], al[mf][3], bh0, bh1);
                }
            }
        }
    }

    // epilogue: D rows g / g+8, cols 2t / 2t+1 within each 16x8 fragment
#pragma unroll
    for (int mf = 0; mf < 2; mf++) {
        int r0 = m0 + wm * 32 + mf * 16 + g;
#pragma unroll
        for (int nf = 0; nf < 8; nf++) {
            int col = n0 + wn * 64 + nf * 8 + 2 * t;
            float* p0 = C + (size_t)r0 * N + col;
            float* p1 = C + (size_t)(r0 + 8) * N + col;
            *(float2*)p0 = make_float2(acc[mf][nf][0], acc[mf][nf][1]);
            *(float2*)p1 = make_float2(acc[mf][nf][2], acc[mf][nf][3]);
        }
    }
}

// ================= RoPE apply + transpose to [B*H, T, D] ======================
__global__ void rope_apply_kernel(const float* __restrict__ qkv,
                                  const float* __restrict__ gcos,
                                  const float* __restrict__ gsin,
                                  float* __restrict__ q, float* __restrict__ k,
                                  float* __restrict__ v) {
    long long idx = (long long)blockIdx.x * blockDim.x + threadIdx.x;
    const long long total = (long long)BATCH * NH * SEQ * DH;
    if (idx >= total) return;
    int d  = (int)(idx & 127);
    int t  = (int)((idx >> 7) & (SEQ - 1));
    int bh = (int)(idx >> 18);
    int b  = bh >> 4;
    int h  = bh & 15;

    size_t base = ((size_t)(b * SEQ + t)) * QKV_N + (size_t)h * DH;
    float qv = qkv[base + d];
    float kv = qkv[base + NEMBD + d];
    float vv = qkv[base + 2 * NEMBD + d];

    int ci = d & 63;
    float c = gcos[t * 64 + ci];
    float s = gsin[t * 64 + ci];
    float qr, kr;
    if (d < 64) {
        qr = -qkv[base + d + 64];
        kr = -qkv[base + NEMBD + d + 64];
    } else {
        qr = qkv[base + d - 64];
        kr = qkv[base + NEMBD + d - 64];
    }

    size_t o = ((size_t)bh * SEQ + t) * DH + d;
    q[o] = qv * c + qr * s;
    k[o] = kv * c + kr * s;
    v[o] = vv;
}

// ================= flash attention (fp32), BQ=128 BK=64 ======================
#define BQ 128
#define BKT 64
#define QTS_LD 132
#define KS_LD  129
#define PS_LD  68
#define FA_SMEM ((BQ*QTS_LD + BKT*KS_LD + BKT*DH + BQ*PS_LD) * 4)

__global__ __launch_bounds__(256)
void flash_attn_kernel(const float* __restrict__ Qg, const float* __restrict__ Kg,
                       const float* __restrict__ Vg, float* __restrict__ Y) {
    extern __shared__ float smf[];
    float* Qts = smf;
    float* Ks  = Qts + BQ * QTS_LD;
    float* Vs  = Ks + BKT * KS_LD;
    float* Ps  = Vs + BKT * DH;

    int tid = threadIdx.x;
    int tc = tid & 15;
    int tr = tid >> 4;
    int qi = gridDim.x - 1 - blockIdx.x;
    int bh = blockIdx.y;
    int qbase = qi * BQ;

    const float* Qb = Qg + ((size_t)bh * SEQ + qbase) * DH;
    const float* Kb = Kg + (size_t)bh * SEQ * DH;
    const float* Vb = Vg + (size_t)bh * SEQ * DH;

    const float scale = 0.08838834764831845f;

    for (int idx = tid; idx < BQ * 32; idx += 256) {
        int row = idx >> 5, dq = idx & 31;
        float4 qv = *(const float4*)(Qb + (size_t)row * DH + dq * 4);
        Qts[(dq * 4 + 0) * QTS_LD + row] = qv.x * scale;
        Qts[(dq * 4 + 1) * QTS_LD + row] = qv.y * scale;
        Qts[(dq * 4 + 2) * QTS_LD + row] = qv.z * scale;
        Qts[(dq * 4 + 3) * QTS_LD + row] = qv.w * scale;
    }

    float m_i[8], l_i[8], o[8][8];
#pragma unroll
    for (int i = 0; i < 8; i++) {
        m_i[i] = -1e30f;
        l_i[i] = 0.0f;
#pragma unroll
        for (int j = 0; j < 8; j++) o[i][j] = 0.0f;
    }

    int nkt = 2 * qi + 2;
    for (int kt = 0; kt < nkt; kt++) {
        int kbase = kt * BKT;
        __syncthreads();
        for (int idx = tid; idx < BKT * 32; idx += 256) {
            int row = idx >> 5, dq = idx & 31;
            float4 kv = *(const float4*)(Kb + (size_t)(kbase + row) * DH + dq * 4);
            Ks[row * KS_LD + dq * 4 + 0] = kv.x;
            Ks[row * KS_LD + dq * 4 + 1] = kv.y;
            Ks[row * KS_LD + dq * 4 + 2] = kv.z;
            Ks[row * KS_LD + dq * 4 + 3] = kv.w;
            float4 vv = *(const float4*)(Vb + (size_t)(kbase + row) * DH + dq * 4);
            *(float4*)&Vs[row * DH + dq * 4] = vv;
        }
        __syncthreads();

        float s[8][4];
#pragma unroll
        for (int i = 0; i < 8; i++)
#pragma unroll
            for (int j = 0; j < 4; j++) s[i][j] = 0.0f;

#pragma unroll 4
        for (int d = 0; d < DH; d++) {
            const float* qrow = &Qts[d * QTS_LD + tr * 8];
            float4 a0 = *(const float4*)qrow;
            float4 a1 = *(const float4*)(qrow + 4);
            float a[8] = {a0.x, a0.y, a0.z, a0.w, a1.x, a1.y, a1.z, a1.w};
            float b[4];
#pragma unroll
            for (int j = 0; j < 4; j++) b[j] = Ks[(tc * 4 + j) * KS_LD + d];
#pragma unroll
            for (int i = 0; i < 8; i++)
#pragma unroll
                for (int j = 0; j < 4; j++)
                    s[i][j] = fmaf(a[i], b[j], s[i][j]);
        }

        if (kbase + BKT - 1 > qbase) {
#pragma unroll
            for (int i = 0; i < 8; i++) {
                int qg = qbase + tr * 8 + i;
#pragma unroll
                for (int j = 0; j < 4; j++) {
                    int kg = kbase + tc * 4 + j;
                    if (kg > qg) s[i][j] = -1e30f;
                }
            }
        }

#pragma unroll
        for (int i = 0; i < 8; i++) {
            float mx = fmaxf(fmaxf(s[i][0], s[i][1]), fmaxf(s[i][2], s[i][3]));
            mx = fmaxf(mx, __shfl_xor_sync(0xffffffffu, mx, 8));
            mx = fmaxf(mx, __shfl_xor_sync(0xffffffffu, mx, 4));
            mx = fmaxf(mx, __shfl_xor_sync(0xffffffffu, mx, 2));
            mx = fmaxf(mx, __shfl_xor_sync(0xffffffffu, mx, 1));
            float mnew = fmaxf(m_i[i], mx);
            float alpha = __expf(m_i[i] - mnew);
            m_i[i] = mnew;
            float rs = 0.0f;
#pragma unroll
            for (int j = 0; j < 4; j++) {
                float p = __expf(s[i][j] - mnew);
                s[i][j] = p;
                rs += p;
            }
            rs += __shfl_xor_sync(0xffffffffu, rs, 8);
            rs += __shfl_xor_sync(0xffffffffu, rs, 4);
            rs += __shfl_xor_sync(0xffffffffu, rs, 2);
            rs += __shfl_xor_sync(0xffffffffu, rs, 1);
            l_i[i] = l_i[i] * alpha + rs;
#pragma unroll
            for (int j = 0; j < 8; j++) o[i][j] *= alpha;
        }

#pragma unroll
        for (int i = 0; i < 8; i++)
            *(float4*)&Ps[(tr * 8 + i) * PS_LD + tc * 4] =
                make_float4(s[i][0], s[i][1], s[i][2], s[i][3]);
        __syncthreads();

#pragma unroll 2
        for (int k = 0; k < BKT; k++) {
            float4 v0 = *(const float4*)&Vs[k * DH + tc * 8];
            float4 v1 = *(const float4*)&Vs[k * DH + tc * 8 + 4];
            float vv[8] = {v0.x, v0.y, v0.z, v0.w, v1.x, v1.y, v1.z, v1.w};
#pragma unroll
            for (int i = 0; i < 8; i++) {
                float p = Ps[(tr * 8 + i) * PS_LD + k];
#pragma unroll
                for (int j = 0; j < 8; j++)
                    o[i][j] = fmaf(p, vv[j], o[i][j]);
            }
        }
    }

    int b = bh >> 4, h = bh & 15;
#pragma unroll
    for (int i = 0; i < 8; i++) {
        float inv = 1.0f / l_i[i];
        int tg = qbase + tr * 8 + i;
        float* yrow = Y + ((size_t)(b * SEQ + tg)) * NEMBD + h * DH + tc * 8;
        *(float4*)yrow       = make_float4(o[i][0] * inv, o[i][1] * inv,
                                           o[i][2] * inv, o[i][3] * inv);
        *(float4*)(yrow + 4) = make_float4(o[i][4] * inv, o[i][5] * inv,
                                           o[i][6] * inv, o[i][7] * inv);
    }
}

// ================= launch =====================================================
extern "C" void kernel_launch(void* const* d_in, const int* in_sizes, int n_in,
                              void* d_out, int out_size) {
    const float* x      = (const float*)d_in[0];
    const float* w_qkv  = (const float*)d_in[1];
    const float* w_proj = (const float*)d_in[2];
    float* out = (float*)d_out;

    float *qkv, *q, *k, *v, *y, *gc, *gs;
    cudaGetSymbolAddress((void**)&qkv, g_qkv);
    cudaGetSymbolAddress((void**)&q, g_q);
    cudaGetSymbolAddress((void**)&k, g_k);
    cudaGetSymbolAddress((void**)&v, g_v);
    cudaGetSymbolAddress((void**)&y, g_y);
    cudaGetSymbolAddress((void**)&gc, g_cos);
    cudaGetSymbolAddress((void**)&gs, g_sin);

    // 1) RoPE tables
    rope_table_kernel<<<(SEQ * 64 + 255) / 256, 256>>>(gc, gs);

    // 2) QKV projection (bf16-split HMMA)
    gemm_mma_kernel<<<dim3(QKV_N / 128, MROWS / 128), 256>>>(
        x, w_qkv, qkv, MROWS, QKV_N, NEMBD);

    // 3) RoPE + transpose
    {
        long long total = (long long)BATCH * NH * SEQ * DH;
        rope_apply_kernel<<<(unsigned)((total + 255) / 256), 256>>>(qkv, gc, gs, q, k, v);
    }

    // 4) flash attention
    cudaFuncSetAttribute(flash_attn_kernel,
                         cudaFuncAttributeMaxDynamicSharedMemorySize, FA_SMEM);
    flash_attn_kernel<<<dim3(SEQ / BQ, BATCH * NH), 256, FA_SMEM>>>(q, k, v, y);

    // 5) output projection (bf16-split HMMA)
    gemm_mma_kernel<<<dim3(NEMBD / 128, MROWS / 128), 256>>>(
        y, w_proj, out, MROWS, NEMBD, NEMBD);
}

// round 4
// speedup vs baseline: 4.1317x; 1.4600x over previous
#include <cuda_runtime.h>
#include <cuda_bf16.h>
#include <math.h>
#include <stdint.h>

// ---------------- problem constants ----------------
#define NEMBD   2048
#define NH      16
#define DH      128
#define BATCH   2
#define SEQ     2048
#define MROWS   (BATCH*SEQ)     // 4096
#define QKV_N   (3*NEMBD)       // 6144
#define BHN     (BATCH*NH)      // 32

// ---------------- scratch (device globals, no runtime allocs) ----------------
__device__ float g_qkv[(size_t)MROWS * QKV_N];
__device__ float g_q[(size_t)BHN*SEQ*DH];
__device__ __nv_bfloat16 g_khi[(size_t)BHN*SEQ*DH];
__device__ __nv_bfloat16 g_klo[(size_t)BHN*SEQ*DH];
__device__ __nv_bfloat16 g_vhi[(size_t)BHN*SEQ*DH];
__device__ __nv_bfloat16 g_vlo[(size_t)BHN*SEQ*DH];
__device__ float g_y[(size_t)MROWS * NEMBD];
__device__ float g_cos[SEQ*64];
__device__ float g_sin[SEQ*64];

// ================= common asm helpers =================
#define MMA16816(d, a0, a1, a2, a3, b0, b1)                                \
    asm volatile(                                                          \
        "mma.sync.aligned.m16n8k16.row.col.f32.bf16.bf16.f32 "             \
        "{%0,%1,%2,%3}, {%4,%5,%6,%7}, {%8,%9}, {%0,%1,%2,%3};"            \
        : "+f"((d)[0]), "+f"((d)[1]), "+f"((d)[2]), "+f"((d)[3])           \
        : "r"(a0), "r"(a1), "r"(a2), "r"(a3), "r"(b0), "r"(b1))

#define LDSM_X4(r0, r1, r2, r3, addr)                                       \
    asm volatile("ldmatrix.sync.aligned.m8n8.x4.shared.b16 "                \
                 "{%0,%1,%2,%3}, [%4];"                                     \
                 : "=r"(r0), "=r"(r1), "=r"(r2), "=r"(r3) : "r"(addr))

#define LDSM_X4T(r0, r1, r2, r3, addr)                                      \
    asm volatile("ldmatrix.sync.aligned.m8n8.x4.trans.shared.b16 "          \
                 "{%0,%1,%2,%3}, [%4];"                                     \
                 : "=r"(r0), "=r"(r1), "=r"(r2), "=r"(r3) : "r"(addr))

#define CP_ASYNC16(dst, src)                                                \
    asm volatile("cp.async.cg.shared.global [%0], [%1], 16;"                \
                 :: "r"(dst), "l"(src))
#define CP_COMMIT() asm volatile("cp.async.commit_group;" ::: "memory")
#define CP_WAIT1()  asm volatile("cp.async.wait_group 1;" ::: "memory")
#define CP_WAIT0()  asm volatile("cp.async.wait_group 0;" ::: "memory")

__device__ __forceinline__ uint32_t smem_u32(const void* p) {
    uint32_t a;
    asm("{ .reg .u64 t; cvta.to.shared.u64 t, %1; cvt.u32.u64 %0, t; }"
        : "=r"(a) : "l"(p));
    return a;
}

__device__ __forceinline__ void bf16_split2(float x, float y,
                                            uint32_t& hi, uint32_t& lo) {
    __nv_bfloat162 h = __floats2bfloat162_rn(x, y);
    float rx = x - __bfloat162float(__low2bfloat16(h));
    float ry = y - __bfloat162float(__high2bfloat16(h));
    __nv_bfloat162 l = __floats2bfloat162_rn(rx, ry);
    hi = *(uint32_t*)&h;
    lo = *(uint32_t*)&l;
}

// ================= RoPE tables (fp64 angles) =================
__global__ void rope_table_kernel(float* gcos, float* gsin) {
    int idx = blockIdx.x * blockDim.x + threadIdx.x;
    if (idx >= SEQ * 64) return;
    int t = idx >> 6;
    int i = idx & 63;
    double freq = exp(-((double)(2 * i) / 128.0) * log(10000.0));
    double ang = (double)t * freq;
    gcos[idx] = (float)cos(ang);
    gsin[idx] = (float)sin(ang);
}

// ================= bf16-split HMMA GEMM (as R3, validated) ===================
#define SLD 40

__global__ __launch_bounds__(256, 2)
void gemm_mma_kernel(const float* __restrict__ A, const float* __restrict__ W,
                     float* __restrict__ C, int M, int N, int K) {
    __shared__ __nv_bfloat16 AsH[128 * SLD];
    __shared__ __nv_bfloat16 AsL[128 * SLD];
    __shared__ __nv_bfloat16 BsH[128 * SLD];
    __shared__ __nv_bfloat16 BsL[128 * SLD];

    const int tid  = threadIdx.x;
    const int warp = tid >> 5, lane = tid & 31;
    const int g = lane >> 2, t = lane & 3;
    const int wm = warp & 3, wn = warp >> 2;
    const int m0 = blockIdx.y * 128;
    const int n0 = blockIdx.x * 128;

    float acc[2][8][4];
#pragma unroll
    for (int mf = 0; mf < 2; mf++)
#pragma unroll
        for (int nf = 0; nf < 8; nf++)
#pragma unroll
            for (int r = 0; r < 4; r++) acc[mf][nf][r] = 0.0f;

    const int lrow = tid >> 1;
    const int lcg  = (tid & 1) * 16;
    const float* Ag = A + (size_t)(m0 + lrow) * K + lcg;
    const float* Wg = W + (size_t)(n0 + lrow) * K + lcg;

    for (int kt = 0; kt < K; kt += 32) {
        __syncthreads();
#pragma unroll
        for (int q = 0; q < 4; q++) {
            float4 av = *(const float4*)(Ag + kt + q * 4);
            uint32_t h01, l01, h23, l23;
            bf16_split2(av.x, av.y, h01, l01);
            bf16_split2(av.z, av.w, h23, l23);
            int idx = lrow * SLD + lcg + q * 4;
            *(uint2*)&AsH[idx] = make_uint2(h01, h23);
            *(uint2*)&AsL[idx] = make_uint2(l01, l23);

            float4 wv = *(const float4*)(Wg + kt + q * 4);
            bf16_split2(wv.x, wv.y, h01, l01);
            bf16_split2(wv.z, wv.w, h23, l23);
            *(uint2*)&BsH[idx] = make_uint2(h01, h23);
            *(uint2*)&BsL[idx] = make_uint2(l01, l23);
        }
        __syncthreads();

#pragma unroll
        for (int kk = 0; kk < 32; kk += 16) {
            uint32_t ah[2][4], al[2][4];
#pragma unroll
            for (int mf = 0; mf < 2; mf++) {
                int r = wm * 32 + mf * 16 + g;
                const __nv_bfloat16* ph = &AsH[r * SLD + kk + 2 * t];
                ah[mf][0] = *(const uint32_t*)ph;
                ah[mf][1] = *(const uint32_t*)(ph + 8 * SLD);
                ah[mf][2] = *(const uint32_t*)(ph + 8);
                ah[mf][3] = *(const uint32_t*)(ph + 8 * SLD + 8);
                const __nv_bfloat16* pl = &AsL[r * SLD + kk + 2 * t];
                al[mf][0] = *(const uint32_t*)pl;
                al[mf][1] = *(const uint32_t*)(pl + 8 * SLD);
                al[mf][2] = *(const uint32_t*)(pl + 8);
                al[mf][3] = *(const uint32_t*)(pl + 8 * SLD + 8);
            }
#pragma unroll
            for (int nf = 0; nf < 8; nf++) {
                int nr = wn * 64 + nf * 8 + g;
                const __nv_bfloat16* pbh = &BsH[nr * SLD + kk + 2 * t];
                uint32_t bh0 = *(const uint32_t*)pbh;
                uint32_t bh1 = *(const uint32_t*)(pbh + 8);
                const __nv_bfloat16* pbl = &BsL[nr * SLD + kk + 2 * t];
                uint32_t bl0 = *(const uint32_t*)pbl;
                uint32_t bl1 = *(const uint32_t*)(pbl + 8);
#pragma unroll
                for (int mf = 0; mf < 2; mf++) {
                    MMA16816(acc[mf][nf], ah[mf][0], ah[mf][1], ah[mf][2], ah[mf][3], bh0, bh1);
                    MMA16816(acc[mf][nf], ah[mf][0], ah[mf][1], ah[mf][2], ah[mf][3], bl0, bl1);
                    MMA16816(acc[mf][nf], al[mf][0], al[mf][1], al[mf][2], al[mf][3], bh0, bh1);
                }
            }
        }
    }

#pragma unroll
    for (int mf = 0; mf < 2; mf++) {
        int r0 = m0 + wm * 32 + mf * 16 + g;
#pragma unroll
        for (int nf = 0; nf < 8; nf++) {
            int col = n0 + wn * 64 + nf * 8 + 2 * t;
            float* p0 = C + (size_t)r0 * N + col;
            float* p1 = C + (size_t)(r0 + 8) * N + col;
            *(float2*)p0 = make_float2(acc[mf][nf][0], acc[mf][nf][1]);
            *(float2*)p1 = make_float2(acc[mf][nf][2], acc[mf][nf][3]);
        }
    }
}

// ======== RoPE apply + transpose; emit Q fp32 and K/V bf16 hi/lo =============
__global__ void rope_apply_kernel(const float* __restrict__ qkv,
                                  const float* __restrict__ gcos,
                                  const float* __restrict__ gsin,
                                  float* __restrict__ q,
                                  __nv_bfloat16* __restrict__ khi,
                                  __nv_bfloat16* __restrict__ klo,
                                  __nv_bfloat16* __restrict__ vhi,
                                  __nv_bfloat16* __restrict__ vlo) {
    long long idx = (long long)blockIdx.x * blockDim.x + threadIdx.x;
    const long long total = (long long)BHN * SEQ * DH;
    if (idx >= total) return;
    int d  = (int)(idx & 127);
    int t  = (int)((idx >> 7) & (SEQ - 1));
    int bh = (int)(idx >> 18);
    int b  = bh >> 4;
    int h  = bh & 15;

    size_t base = ((size_t)(b * SEQ + t)) * QKV_N + (size_t)h * DH;
    float qv = qkv[base + d];
    float kv = qkv[base + NEMBD + d];
    float vv = qkv[base + 2 * NEMBD + d];

    int ci = d & 63;
    float c = gcos[t * 64 + ci];
    float s = gsin[t * 64 + ci];
    float qr, kr;
    if (d < 64) {
        qr = -qkv[base + d + 64];
        kr = -qkv[base + NEMBD + d + 64];
    } else {
        qr = qkv[base + d - 64];
        kr = qkv[base + NEMBD + d - 64];
    }

    size_t o = ((size_t)bh * SEQ + t) * DH + d;
    q[o] = qv * c + qr * s;

    float kval = kv * c + kr * s;
    __nv_bfloat16 kh = __float2bfloat16(kval);
    khi[o] = kh;
    klo[o] = __float2bfloat16(kval - __bfloat162float(kh));

    __nv_bfloat16 vh = __float2bfloat16(vv);
    vhi[o] = vh;
    vlo[o] = __float2bfloat16(vv - __bfloat162float(vh));
}

// ================= flash attention on HMMA (bf16 split-3) ====================
// CTA: 256 thr (8 warps), BQ=128 (16 rows/warp), key tile 64, double-buffered.
#define FBQ 128
#define FBK 64
#define FLD 136                       // bf16 elems per key row (272 B)
#define ARR_B ((size_t)FBK * FLD * 2) // 17408 B per array
#define STG_B (4 * 17408)             // KH,KL,VH,VL
#define FA2_SMEM (2 * STG_B)          // 139264 B

__global__ __launch_bounds__(256, 1)
void flash_mma_kernel(const float* __restrict__ Qg,
                      const __nv_bfloat16* __restrict__ KH,
                      const __nv_bfloat16* __restrict__ KL,
                      const __nv_bfloat16* __restrict__ VH,
                      const __nv_bfloat16* __restrict__ VL,
                      float* __restrict__ Y) {
    extern __shared__ char smc[];
    const uint32_t sbase = smem_u32(smc);

    const int tid  = threadIdx.x;
    const int w    = tid >> 5, lane = tid & 31;
    const int g    = lane >> 2, t = lane & 3;
    const int qi   = gridDim.x - 1 - blockIdx.x;
    const int bh   = blockIdx.y;
    const int qbase = qi * FBQ;
    const int rowmax_w = qbase + w * 16 + 15;

    const size_t bhoff = (size_t)bh * SEQ * DH;

    // ---- load Q fragments (scaled, split) ----
    const float scale = 0.08838834764831845f;
    uint32_t qh[8][4], ql[8][4];
    {
        const float* q0 = Qg + bhoff + (size_t)(qbase + w * 16 + g) * DH;
        const float* q1 = q0 + 8 * DH;
#pragma unroll
        for (int kf = 0; kf < 8; kf++) {
            float2 v00 = *(const float2*)(q0 + 16 * kf + 2 * t);
            float2 v10 = *(const float2*)(q1 + 16 * kf + 2 * t);
            float2 v01 = *(const float2*)(q0 + 16 * kf + 2 * t + 8);
            float2 v11 = *(const float2*)(q1 + 16 * kf + 2 * t + 8);
            bf16_split2(v00.x * scale, v00.y * scale, qh[kf][0], ql[kf][0]);
            bf16_split2(v10.x * scale, v10.y * scale, qh[kf][1], ql[kf][1]);
            bf16_split2(v01.x * scale, v01.y * scale, qh[kf][2], ql[kf][2]);
            bf16_split2(v11.x * scale, v11.y * scale, qh[kf][3], ql[kf][3]);
        }
    }

    // ldmatrix per-lane byte offsets (within an array)
    const uint32_t lmK = (uint32_t)(((lane & 7) * FLD + (lane >> 3) * 8) * 2);
    const uint32_t lmV = (uint32_t)((((lane & 7) + ((lane >> 3) & 1) * 8) * FLD
                                     + (lane >> 4) * 8) * 2);

    float m0r = -1e30f, m1r = -1e30f, l0r = 0.0f, l1r = 0.0f;
    float o[16][4];
#pragma unroll
    for (int nf = 0; nf < 16; nf++)
#pragma unroll
        for (int r = 0; r < 4; r++) o[nf][r] = 0.0f;

    const int nkt = 2 * qi + 2;

    auto prefetch = [&](int s, int kt) {
        const int kb = kt * FBK;
        const __nv_bfloat16* srcs[4] = {
            KH + bhoff + (size_t)kb * DH, KL + bhoff + (size_t)kb * DH,
            VH + bhoff + (size_t)kb * DH, VL + bhoff + (size_t)kb * DH };
        uint32_t dst0 = sbase + (uint32_t)s * STG_B;
#pragma unroll
        for (int it = 0; it < 16; it++) {
            int i = tid + it * 256;
            int arr = i >> 10, key = (i >> 4) & 63, ch = i & 15;
            const __nv_bfloat16* src = srcs[arr] + key * DH + ch * 8;
            uint32_t dst = dst0 + (uint32_t)(arr * 17408 + key * 272 + ch * 16);
            CP_ASYNC16(dst, src);
        }
    };

    prefetch(0, 0);
    CP_COMMIT();

    for (int kt = 0; kt < nkt; kt++) {
        if (kt + 1 < nkt) {
            prefetch((kt + 1) & 1, kt + 1);
            CP_COMMIT();
            CP_WAIT1();
        } else {
            CP_WAIT0();
        }
        __syncthreads();

        const int kbase = kt * FBK;
        const bool active = (kbase <= rowmax_w);
        if (active) {
            const uint32_t stg = sbase + (uint32_t)(kt & 1) * STG_B;

            // ---- S = Q K^T ----
            float s[8][4];
#pragma unroll
            for (int nf = 0; nf < 8; nf++)
#pragma unroll
                for (int r = 0; r < 4; r++) s[nf][r] = 0.0f;

#pragma unroll
            for (int kf2 = 0; kf2 < 4; kf2++) {
#pragma unroll
                for (int nf = 0; nf < 8; nf++) {
                    uint32_t off = (uint32_t)((nf * 8 * FLD + kf2 * 32) * 2);
                    uint32_t bh0, bh1, bh2, bh3, bl0, bl1, bl2, bl3;
                    LDSM_X4(bh0, bh1, bh2, bh3, stg + lmK + off);
                    LDSM_X4(bl0, bl1, bl2, bl3, stg + 17408u + lmK + off);
                    MMA16816(s[nf], qh[2*kf2][0], qh[2*kf2][1], qh[2*kf2][2], qh[2*kf2][3], bh0, bh1);
                    MMA16816(s[nf], qh[2*kf2][0], qh[2*kf2][1], qh[2*kf2][2], qh[2*kf2][3], bl0, bl1);
                    MMA16816(s[nf], ql[2*kf2][0], ql[2*kf2][1], ql[2*kf2][2], ql[2*kf2][3], bh0, bh1);
                    MMA16816(s[nf], qh[2*kf2+1][0], qh[2*kf2+1][1], qh[2*kf2+1][2], qh[2*kf2+1][3], bh2, bh3);
                    MMA16816(s[nf], qh[2*kf2+1][0], qh[2*kf2+1][1], qh[2*kf2+1][2], qh[2*kf2+1][3], bl2, bl3);
                    MMA16816(s[nf], ql[2*kf2+1][0], ql[2*kf2+1][1], ql[2*kf2+1][2], ql[2*kf2+1][3], bh2, bh3);
                }
            }

            // ---- causal mask ----
            const int row0 = qbase + w * 16 + g;
            const int row1 = row0 + 8;
            if (kbase + FBK - 1 > qbase + w * 16) {
#pragma unroll
                for (int nf = 0; nf < 8; nf++) {
                    int c0 = kbase + 8 * nf + 2 * t;
                    if (c0 > row0)     s[nf][0] = -1e30f;
                    if (c0 + 1 > row0) s[nf][1] = -1e30f;
                    if (c0 > row1)     s[nf][2] = -1e30f;
                    if (c0 + 1 > row1) s[nf][3] = -1e30f;
                }
            }

            // ---- online softmax (rows row0, row1 per lane; reduce over t) ----
            float mx0 = -1e30f, mx1 = -1e30f;
#pragma unroll
            for (int nf = 0; nf < 8; nf++) {
                mx0 = fmaxf(mx0, fmaxf(s[nf][0], s[nf][1]));
                mx1 = fmaxf(mx1, fmaxf(s[nf][2], s[nf][3]));
            }
            mx0 = fmaxf(mx0, __shfl_xor_sync(0xffffffffu, mx0, 1));
            mx0 = fmaxf(mx0, __shfl_xor_sync(0xffffffffu, mx0, 2));
            mx1 = fmaxf(mx1, __shfl_xor_sync(0xffffffffu, mx1, 1));
            mx1 = fmaxf(mx1, __shfl_xor_sync(0xffffffffu, mx1, 2));
            float mn0 = fmaxf(m0r, mx0), mn1 = fmaxf(m1r, mx1);
            float a0 = __expf(m0r - mn0), a1 = __expf(m1r - mn1);
            m0r = mn0; m1r = mn1;
            float rs0 = 0.0f, rs1 = 0.0f;
#pragma unroll
            for (int nf = 0; nf < 8; nf++) {
                s[nf][0] = __expf(s[nf][0] - mn0);
                s[nf][1] = __expf(s[nf][1] - mn0);
                s[nf][2] = __expf(s[nf][2] - mn1);
                s[nf][3] = __expf(s[nf][3] - mn1);
                rs0 += s[nf][0] + s[nf][1];
                rs1 += s[nf][2] + s[nf][3];
            }
            rs0 += __shfl_xor_sync(0xffffffffu, rs0, 1);
            rs0 += __shfl_xor_sync(0xffffffffu, rs0, 2);
            rs1 += __shfl_xor_sync(0xffffffffu, rs1, 1);
            rs1 += __shfl_xor_sync(0xffffffffu, rs1, 2);
            l0r = l0r * a0 + rs0;
            l1r = l1r * a1 + rs1;
#pragma unroll
            for (int nf = 0; nf < 16; nf++) {
                o[nf][0] *= a0; o[nf][1] *= a0;
                o[nf][2] *= a1; o[nf][3] *= a1;
            }

            // ---- O += P V  (P from S regs, split) ----
#pragma unroll
            for (int kf = 0; kf < 4; kf++) {
                uint32_t ph[4], pl[4];
                bf16_split2(s[2*kf][0],   s[2*kf][1],   ph[0], pl[0]);
                bf16_split2(s[2*kf][2],   s[2*kf][3],   ph[1], pl[1]);
                bf16_split2(s[2*kf+1][0], s[2*kf+1][1], ph[2], pl[2]);
                bf16_split2(s[2*kf+1][2], s[2*kf+1][3], ph[3], pl[3]);
                uint32_t voff = (uint32_t)((kf * 16 * FLD) * 2);
#pragma unroll
                for (int nf2 = 0; nf2 < 8; nf2++) {
                    uint32_t off = voff + (uint32_t)(nf2 * 32);
                    uint32_t vh0, vh1, vh2, vh3, vl0, vl1, vl2, vl3;
                    LDSM_X4T(vh0, vh1, vh2, vh3, stg + 34816u + lmV + off);
                    LDSM_X4T(vl0, vl1, vl2, vl3, stg + 52224u + lmV + off);
                    MMA16816(o[2*nf2],   ph[0], ph[1], ph[2], ph[3], vh0, vh1);
                    MMA16816(o[2*nf2],   ph[0], ph[1], ph[2], ph[3], vl0, vl1);
                    MMA16816(o[2*nf2],   pl[0], pl[1], pl[2], pl[3], vh0, vh1);
                    MMA16816(o[2*nf2+1], ph[0], ph[1], ph[2], ph[3], vh2, vh3);
                    MMA16816(o[2*nf2+1], ph[0], ph[1], ph[2], ph[3], vl2, vl3);
                    MMA16816(o[2*nf2+1], pl[0], pl[1], pl[2], pl[3], vh2, vh3);
                }
            }
        }
        __syncthreads();
    }

    // ---- epilogue ----
    const int b = bh >> 4, h = bh & 15;
    const int row0 = qbase + w * 16 + g;
    const float inv0 = 1.0f / l0r, inv1 = 1.0f / l1r;
    float* y0 = Y + ((size_t)(b * SEQ + row0)) * NEMBD + h * DH;
    float* y1 = Y + ((size_t)(b * SEQ + row0 + 8)) * NEMBD + h * DH;
#pragma unroll
    for (int nf = 0; nf < 16; nf++) {
        int col = 8 * nf + 2 * t;
        *(float2*)(y0 + col) = make_float2(o[nf][0] * inv0, o[nf][1] * inv0);
        *(float2*)(y1 + col) = make_float2(o[nf][2] * inv1, o[nf][3] * inv1);
    }
}

// ================= launch =====================================================
extern "C" void kernel_launch(void* const* d_in, const int* in_sizes, int n_in,
                              void* d_out, int out_size) {
    const float* x      = (const float*)d_in[0];
    const float* w_qkv  = (const float*)d_in[1];
    const float* w_proj = (const float*)d_in[2];
    float* out = (float*)d_out;

    float *qkv, *q, *y, *gc, *gs;
    __nv_bfloat16 *khi, *klo, *vhi, *vlo;
    cudaGetSymbolAddress((void**)&qkv, g_qkv);
    cudaGetSymbolAddress((void**)&q, g_q);
    cudaGetSymbolAddress((void**)&khi, g_khi);
    cudaGetSymbolAddress((void**)&klo, g_klo);
    cudaGetSymbolAddress((void**)&vhi, g_vhi);
    cudaGetSymbolAddress((void**)&vlo, g_vlo);
    cudaGetSymbolAddress((void**)&y, g_y);
    cudaGetSymbolAddress((void**)&gc, g_cos);
    cudaGetSymbolAddress((void**)&gs, g_sin);

    // 1) RoPE tables
    rope_table_kernel<<<(SEQ * 64 + 255) / 256, 256>>>(gc, gs);

    // 2) QKV projection (bf16-split HMMA)
    gemm_mma_kernel<<<dim3(QKV_N / 128, MROWS / 128), 256>>>(
        x, w_qkv, qkv, MROWS, QKV_N, NEMBD);

    // 3) RoPE + transpose + K/V pre-split
    {
        long long total = (long long)BHN * SEQ * DH;
        rope_apply_kernel<<<(unsigned)((total + 255) / 256), 256>>>(
            qkv, gc, gs, q, khi, klo, vhi, vlo);
    }

    // 4) flash attention (HMMA)
    cudaFuncSetAttribute(flash_mma_kernel,
                         cudaFuncAttributeMaxDynamicSharedMemorySize, FA2_SMEM);
    flash_mma_kernel<<<dim3(SEQ / FBQ, BHN), 256, FA2_SMEM>>>(
        q, khi, klo, vhi, vlo, y);

    // 5) output projection (bf16-split HMMA)
    gemm_mma_kernel<<<dim3(NEMBD / 128, MROWS / 128), 256>>>(
        y, w_proj, out, MROWS, NEMBD, NEMBD);
}

// round 5
// speedup vs baseline: 4.6986x; 1.1372x over previous
#include <cuda_runtime.h>
#include <cuda_bf16.h>
#include <math.h>
#include <stdint.h>

// ---------------- problem constants ----------------
#define NEMBD   2048
#define NH      16
#define DH      128
#define BATCH   2
#define SEQ     2048
#define MROWS   (BATCH*SEQ)     // 4096
#define QKV_N   (3*NEMBD)       // 6144
#define BHN     (BATCH*NH)      // 32

// ---------------- scratch (device globals, no runtime allocs) ----------------
__device__ float g_qkv[(size_t)MROWS * QKV_N];
__device__ float g_q[(size_t)BHN*SEQ*DH];
__device__ __nv_bfloat16 g_khi[(size_t)BHN*SEQ*DH];
__device__ __nv_bfloat16 g_klo[(size_t)BHN*SEQ*DH];
__device__ __nv_bfloat16 g_vhi[(size_t)BHN*SEQ*DH];
__device__ __nv_bfloat16 g_vlo[(size_t)BHN*SEQ*DH];
__device__ __nv_bfloat16 g_xhi[(size_t)MROWS*NEMBD];
__device__ __nv_bfloat16 g_xlo[(size_t)MROWS*NEMBD];
__device__ __nv_bfloat16 g_wqh[(size_t)QKV_N*NEMBD];
__device__ __nv_bfloat16 g_wql[(size_t)QKV_N*NEMBD];
__device__ __nv_bfloat16 g_wph[(size_t)NEMBD*NEMBD];
__device__ __nv_bfloat16 g_wpl[(size_t)NEMBD*NEMBD];
__device__ __nv_bfloat16 g_yhi[(size_t)MROWS*NEMBD];
__device__ __nv_bfloat16 g_ylo[(size_t)MROWS*NEMBD];
__device__ float g_cos[SEQ*64];
__device__ float g_sin[SEQ*64];

// ================= common asm helpers =================
#define MMA16816(d, a0, a1, a2, a3, b0, b1)                                \
    asm volatile(                                                          \
        "mma.sync.aligned.m16n8k16.row.col.f32.bf16.bf16.f32 "             \
        "{%0,%1,%2,%3}, {%4,%5,%6,%7}, {%8,%9}, {%0,%1,%2,%3};"            \
        : "+f"((d)[0]), "+f"((d)[1]), "+f"((d)[2]), "+f"((d)[3])           \
        : "r"(a0), "r"(a1), "r"(a2), "r"(a3), "r"(b0), "r"(b1))

#define LDSM_X4(r0, r1, r2, r3, addr)                                       \
    asm volatile("ldmatrix.sync.aligned.m8n8.x4.shared.b16 "                \
                 "{%0,%1,%2,%3}, [%4];"                                     \
                 : "=r"(r0), "=r"(r1), "=r"(r2), "=r"(r3) : "r"(addr))

#define LDSM_X4T(r0, r1, r2, r3, addr)                                      \
    asm volatile("ldmatrix.sync.aligned.m8n8.x4.trans.shared.b16 "          \
                 "{%0,%1,%2,%3}, [%4];"                                     \
                 : "=r"(r0), "=r"(r1), "=r"(r2), "=r"(r3) : "r"(addr))

#define CP_ASYNC16(dst, src)                                                \
    asm volatile("cp.async.cg.shared.global [%0], [%1], 16;"                \
                 :: "r"(dst), "l"(src))
#define CP_COMMIT() asm volatile("cp.async.commit_group;" ::: "memory")
#define CP_WAIT1()  asm volatile("cp.async.wait_group 1;" ::: "memory")
#define CP_WAIT0()  asm volatile("cp.async.wait_group 0;" ::: "memory")

__device__ __forceinline__ uint32_t smem_u32(const void* p) {
    uint32_t a;
    asm("{ .reg .u64 t; cvta.to.shared.u64 t, %1; cvt.u32.u64 %0, t; }"
        : "=r"(a) : "l"(p));
    return a;
}

__device__ __forceinline__ void bf16_split2(float x, float y,
                                            uint32_t& hi, uint32_t& lo) {
    __nv_bfloat162 h = __floats2bfloat162_rn(x, y);
    float rx = x - __bfloat162float(__low2bfloat16(h));
    float ry = y - __bfloat162float(__high2bfloat16(h));
    __nv_bfloat162 l = __floats2bfloat162_rn(rx, ry);
    hi = *(uint32_t*)&h;
    lo = *(uint32_t*)&l;
}

// ================= RoPE tables (fp64 angles) =================
__global__ void rope_table_kernel(float* gcos, float* gsin) {
    int idx = blockIdx.x * blockDim.x + threadIdx.x;
    if (idx >= SEQ * 64) return;
    int t = idx >> 6;
    int i = idx & 63;
    double freq = exp(-((double)(2 * i) / 128.0) * log(10000.0));
    double ang = (double)t * freq;
    gcos[idx] = (float)cos(ang);
    gsin[idx] = (float)sin(ang);
}

// ================= fp32 -> bf16 hi/lo split (one-shot pass) ==================
__global__ void split_kernel(const float* __restrict__ src,
                             __nv_bfloat16* __restrict__ hi,
                             __nv_bfloat16* __restrict__ lo, long long n4) {
    long long i = (long long)blockIdx.x * blockDim.x + threadIdx.x;
    if (i >= n4) return;
    float4 v = *(const float4*)(src + i * 4);
    uint32_t h01, l01, h23, l23;
    bf16_split2(v.x, v.y, h01, l01);
    bf16_split2(v.z, v.w, h23, l23);
    *(uint2*)(hi + i * 4) = make_uint2(h01, h23);
    *(uint2*)(lo + i * 4) = make_uint2(l01, l23);
}

// ========== bf16-split HMMA GEMM (pre-split operands, cp.async DB) ==========
// C[M,N] = (AH+AL)[M,K] * (BH+BL)[N,K]^T  (split-3 accumulate)
#define SLD 40
#define GARR 10240                 // bytes per array per stage (128 * 80B)
#define GSTG (4*GARR)              // 40960 B per stage
#define GEMM_SMEM (2*GSTG)         // 81920 B

__global__ __launch_bounds__(256, 2)
void gemm_bf16_kernel(const __nv_bfloat16* __restrict__ AH,
                      const __nv_bfloat16* __restrict__ AL,
                      const __nv_bfloat16* __restrict__ BH,
                      const __nv_bfloat16* __restrict__ BL,
                      float* __restrict__ C, int M, int N, int K) {
    extern __shared__ char gsm[];
    const uint32_t sb = smem_u32(gsm);

    const int tid  = threadIdx.x;
    const int warp = tid >> 5, lane = tid & 31;
    const int g = lane >> 2, t = lane & 3;
    const int wm = warp & 3, wn = warp >> 2;     // 4x2 warps; warp tile 32x64
    const int m0 = blockIdx.y * 128;
    const int n0 = blockIdx.x * 128;
    const int NT = K / 32;

    float acc[2][8][4];
#pragma unroll
    for (int mf = 0; mf < 2; mf++)
#pragma unroll
        for (int nf = 0; nf < 8; nf++)
#pragma unroll
            for (int r = 0; r < 4; r++) acc[mf][nf][r] = 0.0f;

    auto prefetch = [&](int s, int kt) {
#pragma unroll
        for (int it = 0; it < 8; it++) {
            int i = tid + it * 256;
            int arr = i >> 9;            // 0..3 : AH,AL,BH,BL
            int row = (i >> 2) & 127;
            int ch  = i & 3;
            const __nv_bfloat16* src =
                (arr == 0) ? AH + (size_t)(m0 + row) * K :
                (arr == 1) ? AL + (size_t)(m0 + row) * K :
                (arr == 2) ? BH + (size_t)(n0 + row) * K :
                             BL + (size_t)(n0 + row) * K;
            src += kt * 32 + ch * 8;
            uint32_t dst = sb + (uint32_t)(s * GSTG + arr * GARR + row * 80 + ch * 16);
            CP_ASYNC16(dst, src);
        }
    };

    prefetch(0, 0);
    CP_COMMIT();

    for (int kt = 0; kt < NT; kt++) {
        if (kt + 1 < NT) {
            prefetch((kt + 1) & 1, kt + 1);
            CP_COMMIT();
            CP_WAIT1();
        } else {
            CP_WAIT0();
        }
        __syncthreads();

        const __nv_bfloat16* AsH =
            (const __nv_bfloat16*)(gsm + (size_t)(kt & 1) * GSTG);
        const __nv_bfloat16* AsL = AsH + GARR / 2;
        const __nv_bfloat16* BsH = AsH + GARR;
        const __nv_bfloat16* BsL = AsH + 3 * GARR / 2;

#pragma unroll
        for (int kk = 0; kk < 32; kk += 16) {
            uint32_t ah[2][4], al[2][4];
#pragma unroll
            for (int mf = 0; mf < 2; mf++) {
                int r = wm * 32 + mf * 16 + g;
                const __nv_bfloat16* ph = &AsH[r * SLD + kk + 2 * t];
                ah[mf][0] = *(const uint32_t*)ph;
                ah[mf][1] = *(const uint32_t*)(ph + 8 * SLD);
                ah[mf][2] = *(const uint32_t*)(ph + 8);
                ah[mf][3] = *(const uint32_t*)(ph + 8 * SLD + 8);
                const __nv_bfloat16* pl = &AsL[r * SLD + kk + 2 * t];
                al[mf][0] = *(const uint32_t*)pl;
                al[mf][1] = *(const uint32_t*)(pl + 8 * SLD);
                al[mf][2] = *(const uint32_t*)(pl + 8);
                al[mf][3] = *(const uint32_t*)(pl + 8 * SLD + 8);
            }
#pragma unroll
            for (int nf = 0; nf < 8; nf++) {
                int nr = wn * 64 + nf * 8 + g;
                const __nv_bfloat16* pbh = &BsH[nr * SLD + kk + 2 * t];
                uint32_t bh0 = *(const uint32_t*)pbh;
                uint32_t bh1 = *(const uint32_t*)(pbh + 8);
                const __nv_bfloat16* pbl = &BsL[nr * SLD + kk + 2 * t];
                uint32_t bl0 = *(const uint32_t*)pbl;
                uint32_t bl1 = *(const uint32_t*)(pbl + 8);
#pragma unroll
                for (int mf = 0; mf < 2; mf++) {
                    MMA16816(acc[mf][nf], ah[mf][0], ah[mf][1], ah[mf][2], ah[mf][3], bh0, bh1);
                    MMA16816(acc[mf][nf], ah[mf][0], ah[mf][1], ah[mf][2], ah[mf][3], bl0, bl1);
                    MMA16816(acc[mf][nf], al[mf][0], al[mf][1], al[mf][2], al[mf][3], bh0, bh1);
                }
            }
        }
        __syncthreads();
    }

#pragma unroll
    for (int mf = 0; mf < 2; mf++) {
        int r0 = m0 + wm * 32 + mf * 16 + g;
#pragma unroll
        for (int nf = 0; nf < 8; nf++) {
            int col = n0 + wn * 64 + nf * 8 + 2 * t;
            float* p0 = C + (size_t)r0 * N + col;
            float* p1 = C + (size_t)(r0 + 8) * N + col;
            *(float2*)p0 = make_float2(acc[mf][nf][0], acc[mf][nf][1]);
            *(float2*)p1 = make_float2(acc[mf][nf][2], acc[mf][nf][3]);
        }
    }
}

// ======== RoPE apply + transpose; emit Q fp32 and K/V bf16 hi/lo =============
__global__ void rope_apply_kernel(const float* __restrict__ qkv,
                                  const float* __restrict__ gcos,
                                  const float* __restrict__ gsin,
                                  float* __restrict__ q,
                                  __nv_bfloat16* __restrict__ khi,
                                  __nv_bfloat16* __restrict__ klo,
                                  __nv_bfloat16* __restrict__ vhi,
                                  __nv_bfloat16* __restrict__ vlo) {
    long long idx = (long long)blockIdx.x * blockDim.x + threadIdx.x;
    const long long total = (long long)BHN * SEQ * DH;
    if (idx >= total) return;
    int d  = (int)(idx & 127);
    int t  = (int)((idx >> 7) & (SEQ - 1));
    int bh = (int)(idx >> 18);
    int b  = bh >> 4;
    int h  = bh & 15;

    size_t base = ((size_t)(b * SEQ + t)) * QKV_N + (size_t)h * DH;
    float qv = qkv[base + d];
    float kv = qkv[base + NEMBD + d];
    float vv = qkv[base + 2 * NEMBD + d];

    int ci = d & 63;
    float c = gcos[t * 64 + ci];
    float s = gsin[t * 64 + ci];
    float qr, kr;
    if (d < 64) {
        qr = -qkv[base + d + 64];
        kr = -qkv[base + NEMBD + d + 64];
    } else {
        qr = qkv[base + d - 64];
        kr = qkv[base + NEMBD + d - 64];
    }

    size_t o = ((size_t)bh * SEQ + t) * DH + d;
    q[o] = qv * c + qr * s;

    float kval = kv * c + kr * s;
    __nv_bfloat16 kh = __float2bfloat16(kval);
    khi[o] = kh;
    klo[o] = __float2bfloat16(kval - __bfloat162float(kh));

    __nv_bfloat16 vh = __float2bfloat16(vv);
    vhi[o] = vh;
    vlo[o] = __float2bfloat16(vv - __bfloat162float(vh));
}

// ================= flash attention on HMMA (bf16 split-3) ====================
#define FBQ 128
#define FBK 64
#define FLD 136
#define STG_B (4 * 17408)
#define FA2_SMEM (2 * STG_B)

__global__ __launch_bounds__(256, 1)
void flash_mma_kernel(const float* __restrict__ Qg,
                      const __nv_bfloat16* __restrict__ KH,
                      const __nv_bfloat16* __restrict__ KL,
                      const __nv_bfloat16* __restrict__ VH,
                      const __nv_bfloat16* __restrict__ VL,
                      __nv_bfloat16* __restrict__ Yh,
                      __nv_bfloat16* __restrict__ Yl) {
    extern __shared__ char smc[];
    const uint32_t sbase = smem_u32(smc);

    const int tid  = threadIdx.x;
    const int w    = tid >> 5, lane = tid & 31;
    const int g    = lane >> 2, t = lane & 3;
    const int qi   = gridDim.x - 1 - blockIdx.x;
    const int bh   = blockIdx.y;
    const int qbase = qi * FBQ;
    const int rowmax_w = qbase + w * 16 + 15;

    const size_t bhoff = (size_t)bh * SEQ * DH;

    const float scale = 0.08838834764831845f;
    uint32_t qh[8][4], ql[8][4];
    {
        const float* q0 = Qg + bhoff + (size_t)(qbase + w * 16 + g) * DH;
        const float* q1 = q0 + 8 * DH;
#pragma unroll
        for (int kf = 0; kf < 8; kf++) {
            float2 v00 = *(const float2*)(q0 + 16 * kf + 2 * t);
            float2 v10 = *(const float2*)(q1 + 16 * kf + 2 * t);
            float2 v01 = *(const float2*)(q0 + 16 * kf + 2 * t + 8);
            float2 v11 = *(const float2*)(q1 + 16 * kf + 2 * t + 8);
            bf16_split2(v00.x * scale, v00.y * scale, qh[kf][0], ql[kf][0]);
            bf16_split2(v10.x * scale, v10.y * scale, qh[kf][1], ql[kf][1]);
            bf16_split2(v01.x * scale, v01.y * scale, qh[kf][2], ql[kf][2]);
            bf16_split2(v11.x * scale, v11.y * scale, qh[kf][3], ql[kf][3]);
        }
    }

    const uint32_t lmK = (uint32_t)(((lane & 7) * FLD + (lane >> 3) * 8) * 2);
    const uint32_t lmV = (uint32_t)((((lane & 7) + ((lane >> 3) & 1) * 8) * FLD
                                     + (lane >> 4) * 8) * 2);

    float m0r = -1e30f, m1r = -1e30f, l0r = 0.0f, l1r = 0.0f;
    float o[16][4];
#pragma unroll
    for (int nf = 0; nf < 16; nf++)
#pragma unroll
        for (int r = 0; r < 4; r++) o[nf][r] = 0.0f;

    const int nkt = 2 * qi + 2;

    auto prefetch = [&](int s, int kt) {
        const int kb = kt * FBK;
        const __nv_bfloat16* srcs[4] = {
            KH + bhoff + (size_t)kb * DH, KL + bhoff + (size_t)kb * DH,
            VH + bhoff + (size_t)kb * DH, VL + bhoff + (size_t)kb * DH };
        uint32_t dst0 = sbase + (uint32_t)s * STG_B;
#pragma unroll
        for (int it = 0; it < 16; it++) {
            int i = tid + it * 256;
            int arr = i >> 10, key = (i >> 4) & 63, ch = i & 15;
            const __nv_bfloat16* src = srcs[arr] + key * DH + ch * 8;
            uint32_t dst = dst0 + (uint32_t)(arr * 17408 + key * 272 + ch * 16);
            CP_ASYNC16(dst, src);
        }
    };

    prefetch(0, 0);
    CP_COMMIT();

    for (int kt = 0; kt < nkt; kt++) {
        if (kt + 1 < nkt) {
            prefetch((kt + 1) & 1, kt + 1);
            CP_COMMIT();
            CP_WAIT1();
        } else {
            CP_WAIT0();
        }
        __syncthreads();

        const int kbase = kt * FBK;
        const bool active = (kbase <= rowmax_w);
        if (active) {
            const uint32_t stg = sbase + (uint32_t)(kt & 1) * STG_B;

            float s[8][4];
#pragma unroll
            for (int nf = 0; nf < 8; nf++)
#pragma unroll
                for (int r = 0; r < 4; r++) s[nf][r] = 0.0f;

#pragma unroll
            for (int kf2 = 0; kf2 < 4; kf2++) {
#pragma unroll
                for (int nf = 0; nf < 8; nf++) {
                    uint32_t off = (uint32_t)((nf * 8 * FLD + kf2 * 32) * 2);
                    uint32_t bh0, bh1, bh2, bh3, bl0, bl1, bl2, bl3;
                    LDSM_X4(bh0, bh1, bh2, bh3, stg + lmK + off);
                    LDSM_X4(bl0, bl1, bl2, bl3, stg + 17408u + lmK + off);
                    MMA16816(s[nf], qh[2*kf2][0], qh[2*kf2][1], qh[2*kf2][2], qh[2*kf2][3], bh0, bh1);
                    MMA16816(s[nf], qh[2*kf2][0], qh[2*kf2][1], qh[2*kf2][2], qh[2*kf2][3], bl0, bl1);
                    MMA16816(s[nf], ql[2*kf2][0], ql[2*kf2][1], ql[2*kf2][2], ql[2*kf2][3], bh0, bh1);
                    MMA16816(s[nf], qh[2*kf2+1][0], qh[2*kf2+1][1], qh[2*kf2+1][2], qh[2*kf2+1][3], bh2, bh3);
                    MMA16816(s[nf], qh[2*kf2+1][0], qh[2*kf2+1][1], qh[2*kf2+1][2], qh[2*kf2+1][3], bl2, bl3);
                    MMA16816(s[nf], ql[2*kf2+1][0], ql[2*kf2+1][1], ql[2*kf2+1][2], ql[2*kf2+1][3], bh2, bh3);
                }
            }

            const int row0 = qbase + w * 16 + g;
            const int row1 = row0 + 8;
            if (kbase + FBK - 1 > qbase + w * 16) {
#pragma unroll
                for (int nf = 0; nf < 8; nf++) {
                    int c0 = kbase + 8 * nf + 2 * t;
                    if (c0 > row0)     s[nf][0] = -1e30f;
                    if (c0 + 1 > row0) s[nf][1] = -1e30f;
                    if (c0 > row1)     s[nf][2] = -1e30f;
                    if (c0 + 1 > row1) s[nf][3] = -1e30f;
                }
            }

            float mx0 = -1e30f, mx1 = -1e30f;
#pragma unroll
            for (int nf = 0; nf < 8; nf++) {
                mx0 = fmaxf(mx0, fmaxf(s[nf][0], s[nf][1]));
                mx1 = fmaxf(mx1, fmaxf(s[nf][2], s[nf][3]));
            }
            mx0 = fmaxf(mx0, __shfl_xor_sync(0xffffffffu, mx0, 1));
            mx0 = fmaxf(mx0, __shfl_xor_sync(0xffffffffu, mx0, 2));
            mx1 = fmaxf(mx1, __shfl_xor_sync(0xffffffffu, mx1, 1));
            mx1 = fmaxf(mx1, __shfl_xor_sync(0xffffffffu, mx1, 2));
            float mn0 = fmaxf(m0r, mx0), mn1 = fmaxf(m1r, mx1);
            float a0 = __expf(m0r - mn0), a1 = __expf(m1r - mn1);
            m0r = mn0; m1r = mn1;
            float rs0 = 0.0f, rs1 = 0.0f;
#pragma unroll
            for (int nf = 0; nf < 8; nf++) {
                s[nf][0] = __expf(s[nf][0] - mn0);
                s[nf][1] = __expf(s[nf][1] - mn0);
                s[nf][2] = __expf(s[nf][2] - mn1);
                s[nf][3] = __expf(s[nf][3] - mn1);
                rs0 += s[nf][0] + s[nf][1];
                rs1 += s[nf][2] + s[nf][3];
            }
            rs0 += __shfl_xor_sync(0xffffffffu, rs0, 1);
            rs0 += __shfl_xor_sync(0xffffffffu, rs0, 2);
            rs1 += __shfl_xor_sync(0xffffffffu, rs1, 1);
            rs1 += __shfl_xor_sync(0xffffffffu, rs1, 2);
            l0r = l0r * a0 + rs0;
            l1r = l1r * a1 + rs1;
#pragma unroll
            for (int nf = 0; nf < 16; nf++) {
                o[nf][0] *= a0; o[nf][1] *= a0;
                o[nf][2] *= a1; o[nf][3] *= a1;
            }

#pragma unroll
            for (int kf = 0; kf < 4; kf++) {
                uint32_t ph[4], pl[4];
                bf16_split2(s[2*kf][0],   s[2*kf][1],   ph[0], pl[0]);
                bf16_split2(s[2*kf][2],   s[2*kf][3],   ph[1], pl[1]);
                bf16_split2(s[2*kf+1][0], s[2*kf+1][1], ph[2], pl[2]);
                bf16_split2(s[2*kf+1][2], s[2*kf+1][3], ph[3], pl[3]);
                uint32_t voff = (uint32_t)((kf * 16 * FLD) * 2);
#pragma unroll
                for (int nf2 = 0; nf2 < 8; nf2++) {
                    uint32_t off = voff + (uint32_t)(nf2 * 32);
                    uint32_t vh0, vh1, vh2, vh3, vl0, vl1, vl2, vl3;
                    LDSM_X4T(vh0, vh1, vh2, vh3, stg + 34816u + lmV + off);
                    LDSM_X4T(vl0, vl1, vl2, vl3, stg + 52224u + lmV + off);
                    MMA16816(o[2*nf2],   ph[0], ph[1], ph[2], ph[3], vh0, vh1);
                    MMA16816(o[2*nf2],   ph[0], ph[1], ph[2], ph[3], vl0, vl1);
                    MMA16816(o[2*nf2],   pl[0], pl[1], pl[2], pl[3], vh0, vh1);
                    MMA16816(o[2*nf2+1], ph[0], ph[1], ph[2], ph[3], vh2, vh3);
                    MMA16816(o[2*nf2+1], ph[0], ph[1], ph[2], ph[3], vl2, vl3);
                    MMA16816(o[2*nf2+1], pl[0], pl[1], pl[2], pl[3], vh2, vh3);
                }
            }
        }
        __syncthreads();
    }

    // ---- epilogue: write y directly as bf16 hi/lo split ----
    const int b = bh >> 4, h = bh & 15;
    const int row0 = qbase + w * 16 + g;
    const float inv0 = 1.0f / l0r, inv1 = 1.0f / l1r;
    size_t y0off = ((size_t)(b * SEQ + row0)) * NEMBD + h * DH;
    size_t y1off = ((size_t)(b * SEQ + row0 + 8)) * NEMBD + h * DH;
#pragma unroll
    for (int nf = 0; nf < 16; nf++) {
        int col = 8 * nf + 2 * t;
        uint32_t h0, l0, h1, l1;
        bf16_split2(o[nf][0] * inv0, o[nf][1] * inv0, h0, l0);
        bf16_split2(o[nf][2] * inv1, o[nf][3] * inv1, h1, l1);
        *(uint32_t*)(Yh + y0off + col) = h0;
        *(uint32_t*)(Yl + y0off + col) = l0;
        *(uint32_t*)(Yh + y1off + col) = h1;
        *(uint32_t*)(Yl + y1off + col) = l1;
    }
}

// ================= launch =====================================================
extern "C" void kernel_launch(void* const* d_in, const int* in_sizes, int n_in,
                              void* d_out, int out_size) {
    const float* x      = (const float*)d_in[0];
    const float* w_qkv  = (const float*)d_in[1];
    const float* w_proj = (const float*)d_in[2];
    float* out = (float*)d_out;

    float *qkv, *q, *gc, *gs;
    __nv_bfloat16 *khi, *klo, *vhi, *vlo, *xhi, *xlo, *wqh, *wql, *wph, *wpl, *yhi, *ylo;
    cudaGetSymbolAddress((void**)&qkv, g_qkv);
    cudaGetSymbolAddress((void**)&q, g_q);
    cudaGetSymbolAddress((void**)&khi, g_khi);
    cudaGetSymbolAddress((void**)&klo, g_klo);
    cudaGetSymbolAddress((void**)&vhi, g_vhi);
    cudaGetSymbolAddress((void**)&vlo, g_vlo);
    cudaGetSymbolAddress((void**)&xhi, g_xhi);
    cudaGetSymbolAddress((void**)&xlo, g_xlo);
    cudaGetSymbolAddress((void**)&wqh, g_wqh);
    cudaGetSymbolAddress((void**)&wql, g_wql);
    cudaGetSymbolAddress((void**)&wph, g_wph);
    cudaGetSymbolAddress((void**)&wpl, g_wpl);
    cudaGetSymbolAddress((void**)&yhi, g_yhi);
    cudaGetSymbolAddress((void**)&ylo, g_ylo);
    cudaGetSymbolAddress((void**)&gc, g_cos);
    cudaGetSymbolAddress((void**)&gs, g_sin);

    // 1) RoPE tables + operand splits
    rope_table_kernel<<<(SEQ * 64 + 255) / 256, 256>>>(gc, gs);
    {
        long long n4;
        n4 = (long long)MROWS * NEMBD / 4;
        split_kernel<<<(unsigned)((n4 + 255) / 256), 256>>>(x, xhi, xlo, n4);
        n4 = (long long)QKV_N * NEMBD / 4;
        split_kernel<<<(unsigned)((n4 + 255) / 256), 256>>>(w_qkv, wqh, wql, n4);
        n4 = (long long)NEMBD * NEMBD / 4;
        split_kernel<<<(unsigned)((n4 + 255) / 256), 256>>>(w_proj, wph, wpl, n4);
    }

    // 2) QKV projection (bf16 HMMA, double-buffered)
    cudaFuncSetAttribute(gemm_bf16_kernel,
                         cudaFuncAttributeMaxDynamicSharedMemorySize, GEMM_SMEM);
    gemm_bf16_kernel<<<dim3(QKV_N / 128, MROWS / 128), 256, GEMM_SMEM>>>(
        xhi, xlo, wqh, wql, qkv, MROWS, QKV_N, NEMBD);

    // 3) RoPE + transpose + K/V pre-split
    {
        long long total = (long long)BHN * SEQ * DH;
        rope_apply_kernel<<<(unsigned)((total + 255) / 256), 256>>>(
            qkv, gc, gs, q, khi, klo, vhi, vlo);
    }

    // 4) flash attention (HMMA) -> y split
    cudaFuncSetAttribute(flash_mma_kernel,
                         cudaFuncAttributeMaxDynamicSharedMemorySize, FA2_SMEM);
    flash_mma_kernel<<<dim3(SEQ / FBQ, BHN), 256, FA2_SMEM>>>(
        q, khi, klo, vhi, vlo, yhi, ylo);

    // 5) output projection (bf16 HMMA)
    gemm_bf16_kernel<<<dim3(NEMBD / 128, MROWS / 128), 256, GEMM_SMEM>>>(
        yhi, ylo, wph, wpl, out, MROWS, NEMBD, NEMBD);
}